// round 13
// baseline (speedup 1.0000x reference)
#include <cuda_runtime.h>
#include <cuda_fp16.h>
#include <cstdint>

#define NPOS    2048
#define CIN     256
#define COUT    256
#define BATCH   64
#define TI      4
#define KC      16
#define NCHUNK  (CIN / KC)     // 16
#define NSUPER  8              // superchunks of 32 k
#define THREADS 256

#define XSTRIDE 48
#define XT_BYTES     (BATCH * XSTRIDE)          // 3072 (one pos tile)
#define CHUNK_BYTES  (TI * XT_BYTES)            // 12288 (one 16-k chunk, 4 pos)
#define SS_BYTES     (2 * CHUNK_BYTES)          // 24576 (one superchunk)
#define NSS          4
#define SMEM_MAIN    (NSS * SS_BYTES)           // 98304

// scratch: xt[iq(512)][kc(16)][pos(4)][b(64)][kslot(16)] f16
__device__ __half g_xt[(NPOS / TI) * NCHUNK * TI * BATCH * KC];

static __device__ __forceinline__ uint32_t smem_u32(const void* p) {
    uint32_t a;
    asm("{ .reg .u64 t; cvta.to.shared.u64 t, %1; cvt.u32.u64 %0, t; }"
        : "=r"(a) : "l"(p));
    return a;
}

static __device__ __forceinline__ uint32_t h2pack(float lo, float hi) {
    __half2 h = __floats2half2_rn(lo, hi);
    return *reinterpret_cast<uint32_t*>(&h);
}

static __device__ __forceinline__ void ldsm4(uint32_t addr, uint32_t r[4]) {
    asm volatile("ldmatrix.sync.aligned.m8n8.x4.shared.b16 {%0,%1,%2,%3}, [%4];"
                 : "=r"(r[0]), "=r"(r[1]), "=r"(r[2]), "=r"(r[3]) : "r"(addr));
}

static __device__ __forceinline__ void mma16816(float d[4], const uint32_t a[4],
                                                const uint32_t b0, const uint32_t b1) {
    asm volatile(
        "mma.sync.aligned.m16n8k16.row.col.f32.f16.f16.f32 "
        "{%0,%1,%2,%3}, {%4,%5,%6,%7}, {%8,%9}, {%0,%1,%2,%3};"
        : "+f"(d[0]), "+f"(d[1]), "+f"(d[2]), "+f"(d[3])
        : "r"(a[0]), "r"(a[1]), "r"(a[2]), "r"(a[3]), "r"(b0), "r"(b1));
}

static __device__ __forceinline__ void cp_async16(uint32_t dst, const void* src) {
    asm volatile("cp.async.cg.shared.global [%0], [%1], 16;"
                 :: "r"(dst), "l"(src) : "memory");
}
#define CP_COMMIT() asm volatile("cp.async.commit_group;" ::: "memory")
#define CP_WAIT2()  asm volatile("cp.async.wait_group 2;" ::: "memory")

// k permutation: physical k (within chunk) 4c+d -> halfword slot
static __device__ __forceinline__ int kslot(int kappa) {
    const int c = kappa >> 2, d = kappa & 3;
    return (d < 2) ? (2 * c + d) : (2 * c + d + 6);
}

// ============================================================================
// Pass 1: x[b][c][i] f32 -> xt[iq][kc][pos][b][kslot] f16 (unchanged, r12)
// ============================================================================
__global__ __launch_bounds__(256)
void x_transpose5(const float* __restrict__ x) {
    __shared__ __align__(16) __half st[32 * 256];

    const int tid = threadIdx.x;
    const int bg  = blockIdx.x >> 8;
    const int ib  = (blockIdx.x >> 2) & 63;
    const int ch  = blockIdx.x & 3;
    const int b0  = bg * 16;
    const int i0  = ib * 32;

    for (int kc = 0; kc < 4; ++kc) {
        const int kcg = ch * 4 + kc;
#pragma unroll
        for (int j = 0; j < 4; ++j) {
            const int u  = tid + j * 256;
            const int iq = u & 7;
            const int kp = (u >> 3) & 7;
            const int bl = u >> 6;
            const float* base = x + ((size_t)((b0 + bl) * CIN + kcg * KC + 2 * kp)) * NPOS
                                  + i0 + iq * 4;
            const float4 v0 = *reinterpret_cast<const float4*>(base);
            const float4 v1 = *reinterpret_cast<const float4*>(base + NPOS);
            const int s0   = kslot(2 * kp);
            const int col  = bl * 16 + s0;
            const int unit = col >> 3;
            const int inr  = col & 7;
            const float a[4] = {v0.x, v0.y, v0.z, v0.w};
            const float b[4] = {v1.x, v1.y, v1.z, v1.w};
#pragma unroll
            for (int e = 0; e < 4; ++e) {
                const int i  = iq * 4 + e;
                const int pu = (unit + i + (i >> 2)) & 31;
                *reinterpret_cast<__half2*>(&st[i * 256 + pu * 8 + inr]) =
                    __floats2half2_rn(a[e], b[e]);
            }
        }
        __syncthreads();
#pragma unroll
        for (int j = 0; j < 4; ++j) {
            const int u    = tid + j * 256;
            const int il   = u >> 5;
            const int part = u & 31;
            const int gi   = i0 + il;
            const int pu   = (part + il + (il >> 2)) & 31;
            const uint4 v = *reinterpret_cast<const uint4*>(&st[il * 256 + pu * 8]);
            const size_t dst = (((size_t)(gi >> 2) * NCHUNK + kcg) * TI + (gi & 3)) * 1024
                             + bg * 256 + part * 8;
            *reinterpret_cast<uint4*>(&g_xt[dst]) = v;
        }
        __syncthreads();
    }
}

// ============================================================================
// Main GEMM: cp.async X staging, 8 superchunks, 1 barrier each.
// ============================================================================
__global__ __launch_bounds__(THREADS, 2)
void fc_hmma11_kernel(const float* __restrict__ W,
                      const float* __restrict__ bias,
                      float* __restrict__ out)
{
    extern __shared__ __align__(128) char dsm[];
    const uint32_t sb = smem_u32(dsm);

    const int tid  = threadIdx.x;
    const int wid  = tid >> 5;
    const int lane = tid & 31;

    const int ig = blockIdx.x >> 2;
    const int mq = blockIdx.x & 3;
    const int i0 = ig * TI;

    const int mg = wid & 3;
    const int pg = wid >> 2;

    const int row0 = lane >> 2;
    const int kq   = (lane & 3) * 4;

    const float* Wp[2];
#pragma unroll
    for (int lp = 0; lp < 2; ++lp)
        Wp[lp] = W + ((size_t)(i0 + pg * 2 + lp) * COUT + mq * 64 + mg * 16 + row0) * CIN;

    // xt: superchunk ss = contiguous 8192 hw (16KB) per ig
    const __half* xtss = g_xt + (size_t)ig * (NCHUNK * 4096);

    // cp.async dst offsets (within a superstage) and src offsets, 4 units/thread
    uint32_t cdst[4];
#pragma unroll
    for (int v = 0; v < 4; ++v) {
        const int u = tid + v * THREADS;      // [0,1024)
        const int w = u & 511;
        cdst[v] = (uint32_t)((u >> 9) * CHUNK_BYTES + (w >> 7) * XT_BYTES
                             + ((w >> 1) & 63) * XSTRIDE + (w & 1) * 16);
    }

    float acc[2][8][4];
#pragma unroll
    for (int p = 0; p < 2; ++p)
#pragma unroll
        for (int n = 0; n < 8; ++n)
#pragma unroll
            for (int c = 0; c < 4; ++c) acc[p][n][c] = 0.0f;

    const int bj = lane >> 3, br = lane & 7;
    const uint32_t b_off = (uint32_t)(((bj & 2) * 4 + br) * XSTRIDE + ((bj & 1) << 4));

    float4 q[2][2];
    uint32_t ah[2][4];

    auto ldg_w = [&](int kc) {
        const int kb = kc * KC + kq;
#pragma unroll
        for (int lp = 0; lp < 2; ++lp) {
            q[lp][0] = *reinterpret_cast<const float4*>(Wp[lp] + kb);
            q[lp][1] = *reinterpret_cast<const float4*>(Wp[lp] + 8 * CIN + kb);
        }
    };

    auto cvt_w = [&]() {
#pragma unroll
        for (int lp = 0; lp < 2; ++lp) {
#pragma unroll
            for (int r = 0; r < 2; ++r) {
                const float4 v = q[lp][r];
                ah[lp][r]     = h2pack(v.x, v.y);
                ah[lp][r + 2] = h2pack(v.z, v.w);
            }
        }
    };

    // issue one superchunk's cp.asyncs (or nothing) + always commit a group
    auto cp_issue = [&](int ss) {
        if (ss < NSUPER) {
            const uint32_t stage = sb + (uint32_t)((ss & (NSS - 1)) * SS_BYTES);
            const __half* src = xtss + (size_t)ss * 8192 + tid * 8;
#pragma unroll
            for (int v = 0; v < 4; ++v)
                cp_async16(stage + cdst[v], src + v * THREADS * 8);
        }
        CP_COMMIT();
    };

    auto compute_half = [&](int ss, int h) {
        const uint32_t stage = sb + (uint32_t)((ss & (NSS - 1)) * SS_BYTES) + h * CHUNK_BYTES;
#pragma unroll
        for (int lp = 0; lp < 2; ++lp) {
            const uint32_t hbase = stage + (uint32_t)((pg * 2 + lp) * XT_BYTES) + b_off;
            uint32_t bh[16];
#pragma unroll
            for (int ng = 0; ng < 4; ++ng)
                ldsm4(hbase + (uint32_t)(ng * 16 * XSTRIDE), bh + 4 * ng);
#pragma unroll
            for (int nt = 0; nt < 8; ++nt) {
                const int ng = nt >> 1, t = nt & 1;
                mma16816(acc[lp][nt], ah[lp], bh[ng * 4 + t * 2], bh[ng * 4 + t * 2 + 1]);
            }
        }
    };

    // ---- prologue: 3 groups in flight, W chunk 0 ----
    cp_issue(0);
    cp_issue(1);
    cp_issue(2);
    ldg_w(0);

    for (int ss = 0; ss < NSUPER; ++ss) {
        CP_WAIT2();              // superchunk ss landed
        __syncthreads();         // all warps done with stage (ss-1)&3
        cp_issue(ss + 3);        // refill the stage freed at ss-1
#pragma unroll
        for (int h = 0; h < 2; ++h) {
            const int kc = 2 * ss + h;
            cvt_w();
            if (kc + 1 < NCHUNK) ldg_w(kc + 1);
            compute_half(ss, h);
        }
    }

    // ---- epilogue: pos-pair exchange through smem, float4 stores along i ----
    __syncthreads();
    float2* ep = reinterpret_cast<float2*>(dsm);

#pragma unroll
    for (int half = 0; half < 2; ++half) {
        const int o = mq * 64 + mg * 16 + row0 + half * 8;
        const float bvA = bias[(size_t)(i0 + pg * 2 + 0) * COUT + o];
        const float bvB = bias[(size_t)(i0 + pg * 2 + 1) * COUT + o];

        if (pg == 0) {
#pragma unroll
            for (int nt = 0; nt < 8; ++nt)
#pragma unroll
                for (int cc = 0; cc < 2; ++cc) {
                    const int e = nt * 2 + cc;
                    float2 v;
                    v.x = acc[0][nt][half * 2 + cc] + bvA;
                    v.y = acc[1][nt][half * 2 + cc] + bvB;
                    ep[(mg * 16 + e) * 32 + lane] = v;
                }
        }
        __syncthreads();
        if (pg == 1) {
#pragma unroll
            for (int nt = 0; nt < 8; ++nt)
#pragma unroll
                for (int cc = 0; cc < 2; ++cc) {
                    const int e = nt * 2 + cc;
                    const float2 v01 = ep[(mg * 16 + e) * 32 + lane];
                    float4 v;
                    v.x = v01.x;
                    v.y = v01.y;
                    v.z = acc[0][nt][half * 2 + cc] + bvA;
                    v.w = acc[1][nt][half * 2 + cc] + bvB;
                    const int b = nt * 8 + (lane & 3) * 2 + cc;
                    *reinterpret_cast<float4*>(out + (size_t)(b * COUT + o) * NPOS + i0) = v;
                }
        }
        __syncthreads();
    }
}

extern "C" void kernel_launch(void* const* d_in, const int* in_sizes, int n_in,
                              void* d_out, int out_size) {
    const float* x    = (const float*)d_in[0];
    const float* W    = (const float*)d_in[1];
    const float* bias = (const float*)d_in[2];
    float* out        = (float*)d_out;
    (void)in_sizes; (void)n_in; (void)out_size;

    static int configured = 0;
    if (!configured) {
        cudaFuncSetAttribute(fc_hmma11_kernel,
                             cudaFuncAttributeMaxDynamicSharedMemorySize, SMEM_MAIN);
        configured = 1;
    }

    x_transpose5<<<1024, 256>>>(x);
    fc_hmma11_kernel<<<(NPOS / TI) * 4, THREADS, SMEM_MAIN>>>(W, bias, out);
}

// round 14
// speedup vs baseline: 1.0416x; 1.0416x over previous
#include <cuda_runtime.h>
#include <cuda_fp16.h>
#include <cstdint>

#define NPOS    2048
#define CIN     256
#define COUT    256
#define BATCH   64
#define TI      4
#define KC      16
#define NCHUNK  (CIN / KC)     // 16
#define THREADS 256

// scratch: xt[ig(512)][kc(16)][pos(4)][b(64)][k(16)] f16, natural k order
__device__ __half g_xt[(NPOS / TI) * NCHUNK * TI * BATCH * KC];

static __device__ __forceinline__ uint32_t h2pack(float lo, float hi) {
    __half2 h = __floats2half2_rn(lo, hi);
    return *reinterpret_cast<uint32_t*>(&h);
}

static __device__ __forceinline__ void mma16816(float d[4], const uint32_t a[4],
                                                const uint32_t b0, const uint32_t b1) {
    asm volatile(
        "mma.sync.aligned.m16n8k16.row.col.f32.f16.f16.f32 "
        "{%0,%1,%2,%3}, {%4,%5,%6,%7}, {%8,%9}, {%0,%1,%2,%3};"
        : "+f"(d[0]), "+f"(d[1]), "+f"(d[2]), "+f"(d[3])
        : "r"(a[0]), "r"(a[1]), "r"(a[2]), "r"(a[3]), "r"(b0), "r"(b1));
}

// ============================================================================
// Pass 1: x[b][c][i] f32 -> xt[ig][kc][pos][b][k] f16 (natural k order).
// CTA = 16 b x 32 i x 64 c (4 kc). Grid = 1024.
// ============================================================================
__global__ __launch_bounds__(256)
void x_transpose6(const float* __restrict__ x) {
    __shared__ __align__(16) __half st[32 * 256];   // 16 KB

    const int tid = threadIdx.x;
    const int bg  = blockIdx.x >> 8;            // 0..3
    const int ib  = (blockIdx.x >> 2) & 63;     // 0..63
    const int ch  = blockIdx.x & 3;             // 0..3
    const int b0  = bg * 16;
    const int i0  = ib * 32;

    for (int kc = 0; kc < 4; ++kc) {
        const int kcg = ch * 4 + kc;

        // ---- Phase A: coalesced reads, half2 STS into swizzled smem ----
#pragma unroll
        for (int j = 0; j < 4; ++j) {
            const int u  = tid + j * 256;        // [0,1024)
            const int iq = u & 7;
            const int kp = (u >> 3) & 7;         // k pair = 2*kp
            const int bl = u >> 6;               // 0..15
            const float* base = x + ((size_t)((b0 + bl) * CIN + kcg * KC + 2 * kp)) * NPOS
                                  + i0 + iq * 4;
            const float4 v0 = *reinterpret_cast<const float4*>(base);
            const float4 v1 = *reinterpret_cast<const float4*>(base + NPOS);
            const int col  = bl * 16 + 2 * kp;   // natural order
            const int unit = col >> 3;
            const int inr  = col & 7;
            const float a[4] = {v0.x, v0.y, v0.z, v0.w};
            const float b[4] = {v1.x, v1.y, v1.z, v1.w};
#pragma unroll
            for (int e = 0; e < 4; ++e) {
                const int i  = iq * 4 + e;
                const int pu = (unit + i + (i >> 2)) & 31;
                *reinterpret_cast<__half2*>(&st[i * 256 + pu * 8 + inr]) =
                    __floats2half2_rn(a[e], b[e]);
            }
        }
        __syncthreads();

        // ---- Phase B: warp-contiguous 512B writes per (i, kc) ----
#pragma unroll
        for (int j = 0; j < 4; ++j) {
            const int u    = tid + j * 256;      // [0,1024)
            const int il   = u >> 5;
            const int part = u & 31;
            const int gi   = i0 + il;
            const int pu   = (part + il + (il >> 2)) & 31;
            const uint4 v = *reinterpret_cast<const uint4*>(&st[il * 256 + pu * 8]);
            const size_t dst = (((size_t)(gi >> 2) * NCHUNK + kcg) * TI + (gi & 3)) * 1024
                             + bg * 256 + part * 8;
            *reinterpret_cast<uint4*>(&g_xt[dst]) = v;
        }
        __syncthreads();
    }
}

// ============================================================================
// Main GEMM: zero-barrier mainloop. B frags LDG.64 direct from xt,
// W frags LDG.128 direct from GMEM, f16 hi-only, fp32 acc.
// 256 thr (2 CTAs/SM), TI=4, M-quarter split, exchange epilogue.
// ============================================================================
__global__ __launch_bounds__(THREADS, 2)
void fc_hmma12_kernel(const float* __restrict__ W,     // [N_POS, C_OUT, C_IN]
                      const float* __restrict__ bias,  // [N_POS, C_OUT]
                      float* __restrict__ out)         // [B, C_OUT, N_POS]
{
    __shared__ __align__(16) float2 ep[64 * 32];       // 16 KB epilogue exchange

    const int tid  = threadIdx.x;
    const int wid  = tid >> 5;               // 8 warps
    const int lane = tid & 31;

    const int ig = blockIdx.x >> 2;          // i-quad group
    const int mq = blockIdx.x & 3;           // M quarter (64 rows)
    const int i0 = ig * TI;

    const int mg = wid & 3;                  // M group (16 rows)
    const int pg = wid >> 2;                 // pos-pair group

    const int row0 = lane >> 2;
    const int kq   = (lane & 3) * 4;

    const float* Wp[2];
#pragma unroll
    for (int lp = 0; lp < 2; ++lp)
        Wp[lp] = W + ((size_t)(i0 + pg * 2 + lp) * COUT + mq * 64 + mg * 16 + row0) * CIN;

    // B base: xt[ig] + pos offset + lane's (b-quarter, k-quad) offset (bytes)
    const char* bbase = reinterpret_cast<const char*>(g_xt + (size_t)ig * (NCHUNK * 4096))
                      + (pg * 2) * 2048 + (lane >> 2) * 32 + (lane & 3) * 8;

    float acc[2][8][4];
#pragma unroll
    for (int p = 0; p < 2; ++p)
#pragma unroll
        for (int n = 0; n < 8; ++n)
#pragma unroll
            for (int c = 0; c < 4; ++c) acc[p][n][c] = 0.0f;

    float4 q[2][2];
    uint32_t ah[2][4];
    uint2 B0[8], B1[8];

    auto ldg_w = [&](int kc) {
        const int kb = kc * KC + kq;
#pragma unroll
        for (int lp = 0; lp < 2; ++lp) {
            q[lp][0] = *reinterpret_cast<const float4*>(Wp[lp] + kb);
            q[lp][1] = *reinterpret_cast<const float4*>(Wp[lp] + 8 * CIN + kb);
        }
    };

    auto cvt_w = [&]() {
#pragma unroll
        for (int lp = 0; lp < 2; ++lp) {
#pragma unroll
            for (int r = 0; r < 2; ++r) {
                const float4 v = q[lp][r];
                ah[lp][r]     = h2pack(v.x, v.y);
                ah[lp][r + 2] = h2pack(v.z, v.w);
            }
        }
    };

    auto ldg_b = [&](int kc, int lp, uint2* B) {
        const char* p = bbase + kc * 8192 + lp * 2048;
#pragma unroll
        for (int nt = 0; nt < 8; ++nt)
            B[nt] = *reinterpret_cast<const uint2*>(p + nt * 256);
    };

    auto mma_lp = [&](int lp, const uint2* B) {
#pragma unroll
        for (int nt = 0; nt < 8; ++nt)
            mma16816(acc[lp][nt], ah[lp], B[nt].x, B[nt].y);
    };

    // ---- prologue ----
    ldg_w(0);
    ldg_b(0, 0, B0);
    ldg_b(0, 1, B1);

#pragma unroll
    for (int kc = 0; kc < NCHUNK; ++kc) {
        cvt_w();                              // consume q(kc)
        if (kc + 1 < NCHUNK) ldg_w(kc + 1);
        mma_lp(0, B0);
        if (kc + 1 < NCHUNK) ldg_b(kc + 1, 0, B0);
        mma_lp(1, B1);
        if (kc + 1 < NCHUNK) ldg_b(kc + 1, 1, B1);
    }

    // ---- epilogue: pos-pair exchange through smem, float4 stores along i ----
    __syncthreads();

#pragma unroll
    for (int half = 0; half < 2; ++half) {
        const int o = mq * 64 + mg * 16 + row0 + half * 8;
        const float bvA = bias[(size_t)(i0 + pg * 2 + 0) * COUT + o];
        const float bvB = bias[(size_t)(i0 + pg * 2 + 1) * COUT + o];

        if (pg == 0) {
#pragma unroll
            for (int nt = 0; nt < 8; ++nt)
#pragma unroll
                for (int cc = 0; cc < 2; ++cc) {
                    const int e = nt * 2 + cc;
                    float2 v;
                    v.x = acc[0][nt][half * 2 + cc] + bvA;
                    v.y = acc[1][nt][half * 2 + cc] + bvB;
                    ep[(mg * 16 + e) * 32 + lane] = v;
                }
        }
        __syncthreads();
        if (pg == 1) {
#pragma unroll
            for (int nt = 0; nt < 8; ++nt)
#pragma unroll
                for (int cc = 0; cc < 2; ++cc) {
                    const int e = nt * 2 + cc;
                    const float2 v01 = ep[(mg * 16 + e) * 32 + lane];
                    float4 v;
                    v.x = v01.x;
                    v.y = v01.y;
                    v.z = acc[0][nt][half * 2 + cc] + bvA;
                    v.w = acc[1][nt][half * 2 + cc] + bvB;
                    const int b = nt * 8 + (lane & 3) * 2 + cc;
                    *reinterpret_cast<float4*>(out + (size_t)(b * COUT + o) * NPOS + i0) = v;
                }
        }
        __syncthreads();
    }
}

extern "C" void kernel_launch(void* const* d_in, const int* in_sizes, int n_in,
                              void* d_out, int out_size) {
    const float* x    = (const float*)d_in[0];
    const float* W    = (const float*)d_in[1];
    const float* bias = (const float*)d_in[2];
    float* out        = (float*)d_out;
    (void)in_sizes; (void)n_in; (void)out_size;

    x_transpose6<<<1024, 256>>>(x);
    fc_hmma12_kernel<<<(NPOS / TI) * 4, THREADS>>>(W, bias, out);
}